// round 11
// baseline (speedup 1.0000x reference)
#include <cuda_runtime.h>
#include <math.h>

#define THREADS 256
#define BPSM    7
#define BLOCKS  912            // even; 456 CTAs per tensor pair; exactly 6/SM
#define TILE4   1024           // float4 per tile = 16 KB contiguous per stream

// ---------------- device-global scratch (zero-init; last block resets to 0
// after every replay, so the graph is replay-clean) -------------------------------
__device__ double       g_S1[2];      // sum p   over non-positive elems (via pu)
__device__ double       g_S2[2];      // sum p^2 over non-positive elems (via pu^2)
__device__ double       g_KT[2];      // sum t (count of positives)
__device__ unsigned int g_maxkey[2];  // max of ~fkey(min positive p); identity 0
__device__ unsigned int g_count;      // blocks-done counter

// ordered-uint key: p smaller <=> fkey smaller <=> ~fkey larger (atomicMax, id 0)
__device__ __forceinline__ unsigned int fkey(float f) {
    unsigned int b = __float_as_uint(f);
    return (b & 0x80000000u) ? ~b : (b | 0x80000000u);
}
__device__ __forceinline__ float funkey(unsigned int k) {
    unsigned int b = (k & 0x80000000u) ? (k & 0x7fffffffu) : ~k;
    return __uint_as_float(b);
}

// Branchless per-element accumulate. t is exactly 0.0 or 1.0, so
//   pu = p*(1-t) = fmaf(-p, t, p) is EXACT (either p or 0.0).
#define ACC(P, T)                                                \
    do {                                                         \
        float _p = (P), _t = (T);                                \
        float _pu = fmaf(-_p, _t, _p);                           \
        S1 += _pu;                                               \
        S2 = fmaf(_pu, _pu, S2);                                 \
        KT += _t;                                                \
        MN = fminf(MN, (_t > 0.5f) ? _p : 1e30f);                \
    } while (0)

#define ACC4(PV, TV)                                             \
    do {                                                         \
        ACC((PV).x, (TV).x); ACC((PV).y, (TV).y);                \
        ACC((PV).z, (TV).z); ACC((PV).w, (TV).w);                \
    } while (0)

// ---------------- single fused kernel --------------------------------------------
// Even blocks process (ap,at); odd blocks (bp,bt). Each CTA owns a CONTIGUOUS run
// of tiles (quotient/remainder split): ~144 KB fully sequential per stream. Within
// a tile, thread t loads float4 offsets {t, t+256, t+512, t+768}: every LDG is
// warp-coalesced (512B/warp), 8 LDG.128 batched per iteration.
__global__ void __launch_bounds__(THREADS, BPSM) union_loss_kernel(
    const float4* __restrict__ ap4, const float4* __restrict__ at4,
    const float4* __restrict__ bp4, const float4* __restrict__ bt4,
    float* __restrict__ out, int n4, int ntail, double inv_n, double n_total)
{
    const int s    = blockIdx.x & 1;           // tensor selector
    const int bid  = blockIdx.x >> 1;          // index within this tensor's CTA set
    const int half = gridDim.x >> 1;

    const float4* __restrict__ p4 = s ? bp4 : ap4;
    const float4* __restrict__ t4 = s ? bt4 : at4;

    float S1 = 0.f, S2 = 0.f, KT = 0.f, MN = 1e30f;

    // contiguous tile range for this CTA: standard quotient/remainder split
    const int n_tiles = n4 >> 10;              // n4 / TILE4
    const int q = n_tiles / half;
    const int r = n_tiles - q * half;
    const int t_begin = bid * q + min(bid, r);
    const int t_end   = t_begin + q + (bid < r ? 1 : 0);

    for (int tile = t_begin; tile < t_end; tile++) {
        int base = tile * TILE4 + threadIdx.x;
        float4 p0 = __ldcs(p4 + base);                float4 q0 = __ldcs(t4 + base);
        float4 p1 = __ldcs(p4 + base + THREADS);      float4 q1 = __ldcs(t4 + base + THREADS);
        float4 p2 = __ldcs(p4 + base + 2 * THREADS);  float4 q2 = __ldcs(t4 + base + 2 * THREADS);
        float4 p3 = __ldcs(p4 + base + 3 * THREADS);  float4 q3 = __ldcs(t4 + base + 3 * THREADS);
        ACC4(p0, q0); ACC4(p1, q1); ACC4(p2, q2); ACC4(p3, q3);
    }
    // remainder float4s (n4 % TILE4)
    for (int i = (n_tiles << 10) + bid * THREADS + threadIdx.x; i < n4;
         i += half * THREADS) {
        float4 p0 = __ldcs(p4 + i); float4 q0 = __ldcs(t4 + i);
        ACC4(p0, q0);
    }
    // scalar tail (n % 4)
    const float* pf = reinterpret_cast<const float*>(p4);
    const float* tf = reinterpret_cast<const float*>(t4);
    if (bid == 0 && threadIdx.x < ntail) {
        int idx = n4 * 4 + threadIdx.x;
        ACC(pf[idx], tf[idx]);
    }

    // ---- warp reduce ----
    #pragma unroll
    for (int o = 16; o > 0; o >>= 1) {
        S1 += __shfl_down_sync(0xffffffffu, S1, o);
        S2 += __shfl_down_sync(0xffffffffu, S2, o);
        KT += __shfl_down_sync(0xffffffffu, KT, o);
        MN  = fminf(MN, __shfl_down_sync(0xffffffffu, MN, o));
    }

    // ---- block reduce ----
    __shared__ float sh[4][THREADS / 32];
    int wid = threadIdx.x >> 5, lid = threadIdx.x & 31;
    if (lid == 0) {
        sh[0][wid] = S1; sh[1][wid] = S2; sh[2][wid] = KT; sh[3][wid] = MN;
    }
    __syncthreads();
    if (threadIdx.x == 0) {
        float v0 = 0.f, v1 = 0.f, v2 = 0.f, mn = 1e30f;
        #pragma unroll
        for (int w = 0; w < THREADS / 32; w++) {
            v0 += sh[0][w]; v1 += sh[1][w]; v2 += sh[2][w]; mn = fminf(mn, sh[3][w]);
        }
        atomicAdd(&g_S1[s], (double)v0);
        atomicAdd(&g_S2[s], (double)v1);
        atomicAdd(&g_KT[s], (double)v2);
        atomicMax(&g_maxkey[s], ~fkey(mn));
    }

    // ---- last-block finalize (threadfence-reduction pattern) ----
    __shared__ int sh_last;
    __shared__ float sh_margin;
    __shared__ int sh_need_fallback;
    __shared__ double sh_base0, sh_base1;
    if (threadIdx.x == 0) {
        __threadfence();
        unsigned int done = atomicAdd(&g_count, 1u);
        sh_last = (done == gridDim.x - 1u);
    }
    __syncthreads();
    if (!sh_last) return;

    if (threadIdx.x == 0) {
        __threadfence();   // acquire: other blocks' atomics visible (L2)
        float sc0 = fminf(1.0f, funkey(~g_maxkey[0]));
        float sc1 = fminf(1.0f, funkey(~g_maxkey[1]));
        float m   = fminf(sc0, sc1);
        double md = (double)m;

        double base[2], bound[2];
        #pragma unroll
        for (int q2 = 0; q2 < 2; q2++) {
            double kk = n_total - g_KT[q2];    // # non-positive elements (exact)
            base[q2]  = 0.5 * g_S2[q2] - md * g_S1[q2] + 0.5 * md * md * kk;
            bound[q2] = 0.5 * md * md * kk;    // >= exact correction from p<m elems
        }
        bool valid = (bound[0] <= 1e-7 * fabs(base[0])) &&
                     (bound[1] <= 1e-7 * fabs(base[1]));
        sh_need_fallback = !valid;
        sh_margin = m;
        sh_base0 = base[0];
        sh_base1 = base[1];
        if (valid) {
            out[0] = (float)(base[0] * inv_n);
            out[1] = (float)(base[1] * inv_n);
        }
        // reset globals for next graph replay
        #pragma unroll
        for (int q2 = 0; q2 < 2; q2++) {
            g_S1[q2] = 0.0; g_S2[q2] = 0.0; g_KT[q2] = 0.0; g_maxkey[q2] = 0u;
        }
        g_count = 0u;
    }
    __syncthreads();
    if (!sh_need_fallback) return;

    // ---- exact correction fallback (single block; never taken on this data) ----
    {
        const float* ap = reinterpret_cast<const float*>(ap4);
        const float* at = reinterpret_cast<const float*>(at4);
        const float* bp = reinterpret_cast<const float*>(bp4);
        const float* bt = reinterpret_cast<const float*>(bt4);
        float m = sh_margin;
        int n = n4 * 4 + ntail;
        double c0 = 0.0, c1 = 0.0;
        for (int j = threadIdx.x; j < n; j += THREADS) {
            float p = ap[j], t = at[j];
            if (!(t > 0.5f) && p < m) { double d = (double)m - (double)p; c0 += 0.5 * d * d; }
            p = bp[j]; t = bt[j];
            if (!(t > 0.5f) && p < m) { double d = (double)m - (double)p; c1 += 0.5 * d * d; }
        }
        __shared__ double shd0[THREADS], shd1[THREADS];
        shd0[threadIdx.x] = c0; shd1[threadIdx.x] = c1;
        __syncthreads();
        for (int o = THREADS / 2; o > 0; o >>= 1) {
            if (threadIdx.x < o) { shd0[threadIdx.x] += shd0[threadIdx.x + o];
                                   shd1[threadIdx.x] += shd1[threadIdx.x + o]; }
            __syncthreads();
        }
        if (threadIdx.x == 0) {
            out[0] = (float)((sh_base0 - shd0[0]) * inv_n);
            out[1] = (float)((sh_base1 - shd1[0]) * inv_n);
        }
    }
}

// ---------------- launch ---------------------------------------------------------
extern "C" void kernel_launch(void* const* d_in, const int* in_sizes, int n_in,
                              void* d_out, int out_size)
{
    const float* ap = (const float*)d_in[0];   // asso_predict
    const float* at = (const float*)d_in[1];   // asso_target
    const float* bp = (const float*)d_in[2];   // attr_predict
    const float* bt = (const float*)d_in[3];   // attr_target
    int n = in_sizes[0];
    int n4 = n >> 2;
    int ntail = n & 3;
    double inv_n = 1.0 / (double)n;
    float* out = (float*)d_out;

    union_loss_kernel<<<BLOCKS, THREADS>>>(
        (const float4*)ap, (const float4*)at,
        (const float4*)bp, (const float4*)bt,
        out, n4, ntail, inv_n, (double)n);
}

// round 12
// speedup vs baseline: 1.0454x; 1.0454x over previous
#include <cuda_runtime.h>
#include <math.h>

#define THREADS 256
#define BPSM    7
#define BLOCKS  912            // even; 456 CTAs per tensor pair
#define TILE4   1024           // float4 per tile = 16 KB contiguous per stream

// ---------------- device-global scratch (zero-init; last block resets to 0
// after every replay, so the graph is replay-clean) -------------------------------
__device__ double       g_S1[2];      // sum p   over non-positive elems (via pu)
__device__ double       g_S2[2];      // sum p^2 over non-positive elems (via pu^2)
__device__ double       g_KT[2];      // sum t (count of positives)
__device__ unsigned int g_maxkey[2];  // max of ~fkey(min positive p); identity 0
__device__ unsigned int g_count;      // blocks-done counter

// ordered-uint key: p smaller <=> fkey smaller <=> ~fkey larger (atomicMax, id 0)
__device__ __forceinline__ unsigned int fkey(float f) {
    unsigned int b = __float_as_uint(f);
    return (b & 0x80000000u) ? ~b : (b | 0x80000000u);
}
__device__ __forceinline__ float funkey(unsigned int k) {
    unsigned int b = (k & 0x80000000u) ? (k & 0x7fffffffu) : ~k;
    return __uint_as_float(b);
}

// Branchless per-element accumulate. t is exactly 0.0 or 1.0, so
//   pu = p*(1-t) = fmaf(-p, t, p) is EXACT (either p or 0.0).
#define ACC(P, T)                                                \
    do {                                                         \
        float _p = (P), _t = (T);                                \
        float _pu = fmaf(-_p, _t, _p);                           \
        S1 += _pu;                                               \
        S2 = fmaf(_pu, _pu, S2);                                 \
        KT += _t;                                                \
        MN = fminf(MN, (_t > 0.5f) ? _p : 1e30f);                \
    } while (0)

#define ACC4(PV, TV)                                             \
    do {                                                         \
        ACC((PV).x, (TV).x); ACC((PV).y, (TV).y);                \
        ACC((PV).z, (TV).z); ACC((PV).w, (TV).w);                \
    } while (0)

// ---------------- single fused kernel --------------------------------------------
// Even blocks process (ap,at); odd blocks (bp,bt). CTAs walk contiguous 16KB tiles
// with tile-stride; within a tile thread t loads float4 offsets {t, t+256, t+512,
// t+768}: every LDG is warp-coalesced (512B contiguous per warp) and the 8
// in-flight loads per iteration cover two contiguous 16KB windows. Tile-striding
// spreads concurrent CTA addresses uniformly across LTS slices (measured best:
// 5997 GB/s — contiguous runs and megabyte-strided patterns both measure worse).
__global__ void __launch_bounds__(THREADS, BPSM) union_loss_kernel(
    const float4* __restrict__ ap4, const float4* __restrict__ at4,
    const float4* __restrict__ bp4, const float4* __restrict__ bt4,
    float* __restrict__ out, int n4, int ntail, double inv_n, double n_total)
{
    const int s    = blockIdx.x & 1;           // tensor selector
    const int bid  = blockIdx.x >> 1;          // index within this tensor's CTA set
    const int half = gridDim.x >> 1;

    const float4* __restrict__ p4 = s ? bp4 : ap4;
    const float4* __restrict__ t4 = s ? bt4 : at4;

    float S1 = 0.f, S2 = 0.f, KT = 0.f, MN = 1e30f;

    // full 16KB tiles, warp-coalesced within tile
    const int n_tiles = n4 >> 10;              // n4 / TILE4
    for (int tile = bid; tile < n_tiles; tile += half) {
        int base = tile * TILE4 + threadIdx.x;
        float4 p0 = __ldcs(p4 + base);                float4 q0 = __ldcs(t4 + base);
        float4 p1 = __ldcs(p4 + base + THREADS);      float4 q1 = __ldcs(t4 + base + THREADS);
        float4 p2 = __ldcs(p4 + base + 2 * THREADS);  float4 q2 = __ldcs(t4 + base + 2 * THREADS);
        float4 p3 = __ldcs(p4 + base + 3 * THREADS);  float4 q3 = __ldcs(t4 + base + 3 * THREADS);
        ACC4(p0, q0); ACC4(p1, q1); ACC4(p2, q2); ACC4(p3, q3);
    }
    // remainder float4s (n4 % TILE4)
    for (int i = (n_tiles << 10) + bid * THREADS + threadIdx.x; i < n4;
         i += half * THREADS) {
        float4 p0 = __ldcs(p4 + i); float4 q0 = __ldcs(t4 + i);
        ACC4(p0, q0);
    }
    // scalar tail (n % 4)
    const float* pf = reinterpret_cast<const float*>(p4);
    const float* tf = reinterpret_cast<const float*>(t4);
    if (bid == 0 && threadIdx.x < ntail) {
        int idx = n4 * 4 + threadIdx.x;
        ACC(pf[idx], tf[idx]);
    }

    // ---- warp reduce ----
    #pragma unroll
    for (int o = 16; o > 0; o >>= 1) {
        S1 += __shfl_down_sync(0xffffffffu, S1, o);
        S2 += __shfl_down_sync(0xffffffffu, S2, o);
        KT += __shfl_down_sync(0xffffffffu, KT, o);
        MN  = fminf(MN, __shfl_down_sync(0xffffffffu, MN, o));
    }

    // ---- block reduce ----
    __shared__ float sh[4][THREADS / 32];
    int wid = threadIdx.x >> 5, lid = threadIdx.x & 31;
    if (lid == 0) {
        sh[0][wid] = S1; sh[1][wid] = S2; sh[2][wid] = KT; sh[3][wid] = MN;
    }
    __syncthreads();
    if (threadIdx.x == 0) {
        float v0 = 0.f, v1 = 0.f, v2 = 0.f, mn = 1e30f;
        #pragma unroll
        for (int w = 0; w < THREADS / 32; w++) {
            v0 += sh[0][w]; v1 += sh[1][w]; v2 += sh[2][w]; mn = fminf(mn, sh[3][w]);
        }
        atomicAdd(&g_S1[s], (double)v0);
        atomicAdd(&g_S2[s], (double)v1);
        atomicAdd(&g_KT[s], (double)v2);
        atomicMax(&g_maxkey[s], ~fkey(mn));
    }

    // ---- last-block finalize (threadfence-reduction pattern) ----
    __shared__ int sh_last;
    __shared__ float sh_margin;
    __shared__ int sh_need_fallback;
    __shared__ double sh_base0, sh_base1;
    if (threadIdx.x == 0) {
        __threadfence();
        unsigned int done = atomicAdd(&g_count, 1u);
        sh_last = (done == gridDim.x - 1u);
    }
    __syncthreads();
    if (!sh_last) return;

    if (threadIdx.x == 0) {
        __threadfence();   // acquire: other blocks' atomics visible (L2)
        float sc0 = fminf(1.0f, funkey(~g_maxkey[0]));
        float sc1 = fminf(1.0f, funkey(~g_maxkey[1]));
        float m   = fminf(sc0, sc1);
        double md = (double)m;

        double base[2], bound[2];
        #pragma unroll
        for (int q = 0; q < 2; q++) {
            double kk = n_total - g_KT[q];     // # non-positive elements (exact)
            base[q]  = 0.5 * g_S2[q] - md * g_S1[q] + 0.5 * md * md * kk;
            bound[q] = 0.5 * md * md * kk;     // >= exact correction from p<m elems
        }
        bool valid = (bound[0] <= 1e-7 * fabs(base[0])) &&
                     (bound[1] <= 1e-7 * fabs(base[1]));
        sh_need_fallback = !valid;
        sh_margin = m;
        sh_base0 = base[0];
        sh_base1 = base[1];
        if (valid) {
            out[0] = (float)(base[0] * inv_n);
            out[1] = (float)(base[1] * inv_n);
        }
        // reset globals for next graph replay
        #pragma unroll
        for (int q = 0; q < 2; q++) {
            g_S1[q] = 0.0; g_S2[q] = 0.0; g_KT[q] = 0.0; g_maxkey[q] = 0u;
        }
        g_count = 0u;
    }
    __syncthreads();
    if (!sh_need_fallback) return;

    // ---- exact correction fallback (single block; never taken on this data) ----
    {
        const float* ap = reinterpret_cast<const float*>(ap4);
        const float* at = reinterpret_cast<const float*>(at4);
        const float* bp = reinterpret_cast<const float*>(bp4);
        const float* bt = reinterpret_cast<const float*>(bt4);
        float m = sh_margin;
        int n = n4 * 4 + ntail;
        double c0 = 0.0, c1 = 0.0;
        for (int j = threadIdx.x; j < n; j += THREADS) {
            float p = ap[j], t = at[j];
            if (!(t > 0.5f) && p < m) { double d = (double)m - (double)p; c0 += 0.5 * d * d; }
            p = bp[j]; t = bt[j];
            if (!(t > 0.5f) && p < m) { double d = (double)m - (double)p; c1 += 0.5 * d * d; }
        }
        __shared__ double shd0[THREADS], shd1[THREADS];
        shd0[threadIdx.x] = c0; shd1[threadIdx.x] = c1;
        __syncthreads();
        for (int o = THREADS / 2; o > 0; o >>= 1) {
            if (threadIdx.x < o) { shd0[threadIdx.x] += shd0[threadIdx.x + o];
                                   shd1[threadIdx.x] += shd1[threadIdx.x + o]; }
            __syncthreads();
        }
        if (threadIdx.x == 0) {
            out[0] = (float)((sh_base0 - shd0[0]) * inv_n);
            out[1] = (float)((sh_base1 - shd1[0]) * inv_n);
        }
    }
}

// ---------------- launch ---------------------------------------------------------
extern "C" void kernel_launch(void* const* d_in, const int* in_sizes, int n_in,
                              void* d_out, int out_size)
{
    const float* ap = (const float*)d_in[0];   // asso_predict
    const float* at = (const float*)d_in[1];   // asso_target
    const float* bp = (const float*)d_in[2];   // attr_predict
    const float* bt = (const float*)d_in[3];   // attr_target
    int n = in_sizes[0];
    int n4 = n >> 2;
    int ntail = n & 3;
    double inv_n = 1.0 / (double)n;
    float* out = (float*)d_out;

    union_loss_kernel<<<BLOCKS, THREADS>>>(
        (const float4*)ap, (const float4*)at,
        (const float4*)bp, (const float4*)bt,
        out, n4, ntail, inv_n, (double)n);
}